// round 9
// baseline (speedup 1.0000x reference)
#include <cuda_runtime.h>
#include <math.h>

#define Nn   12288
#define Ee   393216
#define Bb   16
#define FIN  15
#define Hh   32
#define H2   64
#define NC   11

// ---------------- scratch (static device globals; no allocs) ----------------
__device__ float  g_ew[Ee];
__device__ int    g_cnt[Nn];
__device__ int    g_rowptr[Nn + 1];
__device__ int    g_woff[Nn];
__device__ float  g_deg[Nn];
__device__ float2 g_pack[Ee];          // (col bits, val = ew * dis[col])

__device__ float g_x16[Nn * 16];       // x padded 15 -> 16 for float4 gathers
__device__ float g_z1[Nn * Hh];
__device__ float g_z2[Nn * H2];
__device__ float g_z3[Nn * H2];

__device__ float g_sum[3 * 64];
__device__ float g_sq [3 * 64];

__device__ float g_emb[Bb * 64];
__device__ float g_fc1[Bb * 512];
__device__ float g_fc2[Bb * 256];

// ---------------- init + pad x ----------------
__global__ void k_init(const float* __restrict__ x) {
    int i = blockIdx.x * blockDim.x + threadIdx.x;
    if (i < Nn * 16) {
        int f = i & 15;
        g_x16[i] = (f < FIN) ? x[(i >> 4) * FIN + f] : 0.f;
    }
    if (i < Nn) { g_cnt[i] = 0; g_woff[i] = 0; g_deg[i] = 0.f; }
    if (i < 3 * 64) { g_sum[i] = 0.f; g_sq[i] = 0.f; }
    if (i < Bb * 64) g_emb[i] = 0.f;
}

__global__ void k_edge(const float* __restrict__ ea, const float* __restrict__ we,
                       const float* __restrict__ be, const int* __restrict__ ei) {
    int e = blockIdx.x * blockDim.x + threadIdx.x;
    if (e >= Ee) return;
    float2 a = ((const float2*)ea)[e];
    float t = a.x * we[0] + a.y * we[1] + be[0];
    float w = 1.f / (1.f + __expf(-t));
    g_ew[e] = w;
    int r = ei[e];
    atomicAdd(&g_cnt[r], 1);
    atomicAdd(&g_deg[r], w);
}

// single-block exclusive scan of g_cnt -> g_rowptr
__global__ void k_scan() {
    __shared__ int sh[1024];
    int t = threadIdx.x;
    const int C = Nn / 1024;  // 12
    int base = t * C;
    int pre[C];
    int s = 0;
    #pragma unroll
    for (int c = 0; c < C; c++) { pre[c] = s; s += g_cnt[base + c]; }
    sh[t] = s;
    __syncthreads();
    for (int d = 1; d < 1024; d <<= 1) {
        int v = (t >= d) ? sh[t - d] : 0;
        __syncthreads();
        sh[t] += v;
        __syncthreads();
    }
    int off = (t > 0) ? sh[t - 1] : 0;
    #pragma unroll
    for (int c = 0; c < C; c++) g_rowptr[base + c] = off + pre[c];
    if (t == 1023) g_rowptr[Nn] = sh[1023];
}

__global__ void k_scatter(const int* __restrict__ ei) {
    int e = blockIdx.x * blockDim.x + threadIdx.x;
    if (e >= Ee) return;
    int r = ei[e];
    int c = ei[Ee + e];
    float val = g_ew[e] * rsqrtf(1.f + g_deg[c]);
    int p = g_rowptr[r] + atomicAdd(&g_woff[r], 1);
    g_pack[p] = make_float2(__int_as_float(c), val);
}

// ---- fused GCN layer: (BN+ReLU of prev inline) -> SpMM -> GEMM -> BN stats ----
// BN stats accumulate in per-lane REGISTERS across the warp's rows (each lane
// always owns the same feature column), merged via shared atomics once per
// warp at kernel end, then one global atomic per block.
template <int FI, int FIeff, int FO, bool BN_IN, int GRID>
__global__ void __launch_bounds__(256) k_layer(
    const float* __restrict__ in,
    const float* __restrict__ W,         // [FIeff,FO]
    const float* __restrict__ bias,
    const float* __restrict__ gam, const float* __restrict__ bet,
    const float* __restrict__ sum_in, const float* __restrict__ sq_in,
    float* __restrict__ out,
    float* __restrict__ sum_out, float* __restrict__ sq_out)
{
    constexpr int LPE = FI / 4;
    constexpr int EPW = 32 / LPE;
    __shared__ float  sW[FIeff * FO];
    __shared__ float4 sRow4[8][16];
    __shared__ float  sScale[FI], sShift[FI];
    __shared__ float  sSum[FO], sSq[FO];
    int tid = threadIdx.x;
    for (int i = tid; i < FIeff * FO; i += 256) sW[i] = W[i];
    if (tid < FO) { sSum[tid] = 0.f; sSq[tid] = 0.f; }
    if (tid < FI) {
        if (BN_IN) {
            float mu  = sum_in[tid] * (1.f / (float)Nn);
            float var = sq_in[tid]  * (1.f / (float)Nn) - mu * mu;
            float inv = rsqrtf(var + 1e-5f);
            float sc  = gam[tid] * inv;
            sScale[tid] = sc;
            sShift[tid] = bet[tid] - sc * mu;
        } else { sScale[tid] = 1.f; sShift[tid] = 0.f; }
    }
    __syncthreads();

    int warp = tid >> 5, lane = tid & 31;
    int eh = lane / LPE;        // edge slot
    int fl = lane % LPE;        // feature quad
    float4 sc4, sh4;
    sc4.x = sScale[4*fl+0]; sc4.y = sScale[4*fl+1];
    sc4.z = sScale[4*fl+2]; sc4.w = sScale[4*fl+3];
    sh4.x = sShift[4*fl+0]; sh4.y = sShift[4*fl+1];
    sh4.z = sShift[4*fl+2]; sh4.w = sShift[4*fl+3];
    float b0 = (lane < FO) ? bias[lane] : 0.f;
    float b1 = (FO > 32) ? bias[lane + 32] : 0.f;

    // per-lane BN-stat accumulators (registers)
    float rs0 = 0.f, rq0 = 0.f, rs1 = 0.f, rq1 = 0.f;

    const float4* in4 = (const float4*)in;
    const int RPW = Nn / (GRID * 8);
    int rowBase = (blockIdx.x * 8 + warp) * RPW;

    for (int rr = 0; rr < RPW; rr++) {
        int row = rowBase + rr;
        float d = rsqrtf(1.f + g_deg[row]);
        int s = g_rowptr[row], e = g_rowptr[row + 1];

        float4 acc = make_float4(0.f, 0.f, 0.f, 0.f);
        if (eh == 0) {   // self-loop (weight 1): d * bnrelu(in[row])
            float4 v = in4[row * LPE + fl];
            if (BN_IN) {
                v.x = fmaxf(fmaf(sc4.x, v.x, sh4.x), 0.f);
                v.y = fmaxf(fmaf(sc4.y, v.y, sh4.y), 0.f);
                v.z = fmaxf(fmaf(sc4.z, v.z, sh4.z), 0.f);
                v.w = fmaxf(fmaf(sc4.w, v.w, sh4.w), 0.f);
            }
            acc.x = d * v.x; acc.y = d * v.y; acc.z = d * v.z; acc.w = d * v.w;
        }

        for (int k = s; k < e; k += 32) {
            int n = min(32, e - k);
            float2 pk = (lane < n) ? __ldg(&g_pack[k + lane])
                                   : make_float2(__int_as_float(0), 0.f);
            for (int j = 0; j < n; j += EPW) {
                int src = j + eh;
                int   c = __float_as_int(__shfl_sync(0xffffffffu, pk.x, src));
                float w = __shfl_sync(0xffffffffu, pk.y, src);
                float4 v = in4[c * LPE + fl];
                if (BN_IN) {
                    v.x = fmaxf(fmaf(sc4.x, v.x, sh4.x), 0.f);
                    v.y = fmaxf(fmaf(sc4.y, v.y, sh4.y), 0.f);
                    v.z = fmaxf(fmaf(sc4.z, v.z, sh4.z), 0.f);
                    v.w = fmaxf(fmaf(sc4.w, v.w, sh4.w), 0.f);
                }
                acc.x = fmaf(w, v.x, acc.x);
                acc.y = fmaf(w, v.y, acc.y);
                acc.z = fmaf(w, v.z, acc.z);
                acc.w = fmaf(w, v.w, acc.w);
            }
        }
        // reduce over edge slots
        #pragma unroll
        for (int o = LPE; o < 32; o <<= 1) {
            acc.x += __shfl_xor_sync(0xffffffffu, acc.x, o);
            acc.y += __shfl_xor_sync(0xffffffffu, acc.y, o);
            acc.z += __shfl_xor_sync(0xffffffffu, acc.z, o);
            acc.w += __shfl_xor_sync(0xffffffffu, acc.w, o);
        }
        acc.x *= d; acc.y *= d; acc.z *= d; acc.w *= d;
        if (eh == 0) sRow4[warp][fl] = acc;
        __syncwarp();
        const float* h = (const float*)&sRow4[warp][0];
        float o0 = b0, o1 = b1;
        #pragma unroll
        for (int f = 0; f < FIeff; f++) {
            float hv = h[f];
            o0 = fmaf(hv, sW[f * FO + lane], o0);
            if (FO > 32) o1 = fmaf(hv, sW[f * FO + lane + 32], o1);
        }
        __syncwarp();
        if (lane < FO) {
            out[row * FO + lane] = o0;
            rs0 += o0; rq0 = fmaf(o0, o0, rq0);
        }
        if (FO > 32) {
            out[row * FO + lane + 32] = o1;
            rs1 += o1; rq1 = fmaf(o1, o1, rq1);
        }
    }
    // merge per-lane stats: shared atomics once per warp, then global per block
    if (lane < FO) {
        atomicAdd(&sSum[lane], rs0);
        atomicAdd(&sSq[lane],  rq0);
    }
    if (FO > 32) {
        atomicAdd(&sSum[lane + 32], rs1);
        atomicAdd(&sSq[lane + 32],  rq1);
    }
    __syncthreads();
    if (tid < FO) {
        atomicAdd(&sum_out[tid], sSum[tid]);
        atomicAdd(&sq_out[tid],  sSq[tid]);
    }
}

// ---------------- max pool: sorted-batch segment flush ----------------
__global__ void __launch_bounds__(256) k_pool(
    const float* __restrict__ z3, const int* __restrict__ batch,
    const float* __restrict__ gam, const float* __restrict__ bet) {
    __shared__ float scl[64], shf[64];
    int t = threadIdx.x;
    if (t < 64) {
        float mu  = g_sum[128 + t] * (1.f / (float)Nn);
        float var = g_sq [128 + t] * (1.f / (float)Nn) - mu * mu;
        float inv = rsqrtf(var + 1e-5f);
        float sc  = gam[t] * inv;
        scl[t] = sc; shf[t] = bet[t] - sc * mu;
    }
    __syncthreads();
    int f  = t & 63;
    int r0 = blockIdx.x * 128 + (t >> 6);
    float sc = scl[f], sh = shf[f];
    int curb = -1; float cm = 0.f;
    for (int r = r0; r < blockIdx.x * 128 + 128; r += 4) {
        int b = batch[r];
        float v = fmaxf(fmaf(sc, z3[r * 64 + f], sh), 0.f);
        if (b != curb) {
            if (curb >= 0) atomicMax((int*)&g_emb[curb * 64 + f], __float_as_int(cm));
            curb = b; cm = v;
        } else cm = fmaxf(cm, v);
    }
    if (curb >= 0) atomicMax((int*)&g_emb[curb * 64 + f], __float_as_int(cm));
}

// ---------------- MLP head ----------------
__global__ void __launch_bounds__(256) k_mlp1(
    const float* __restrict__ wf1, const float* __restrict__ bf1,
    const float* __restrict__ gf1, const float* __restrict__ bef1,
    float* __restrict__ out) {
    __shared__ float se[16 * 64];
    __shared__ float sz[16][64];
    __shared__ float scl[64], shf[64];
    int t = threadIdx.x;
    for (int i = t; i < 1024; i += 256) se[i] = g_emb[i];
    __syncthreads();
    int cl = t & 63;
    int r0 = t >> 6;
    int c = blockIdx.x * 64 + cl;
    #pragma unroll
    for (int q = 0; q < 4; q++) {
        int r = r0 + q * 4;
        float a0 = 0.f, a1 = 0.f, a2 = 0.f, a3 = 0.f;
        #pragma unroll
        for (int k = 0; k < 64; k += 4) {
            a0 += se[r * 64 + k]     * wf1[(k)     * 512 + c];
            a1 += se[r * 64 + k + 1] * wf1[(k + 1) * 512 + c];
            a2 += se[r * 64 + k + 2] * wf1[(k + 2) * 512 + c];
            a3 += se[r * 64 + k + 3] * wf1[(k + 3) * 512 + c];
        }
        sz[r][cl] = bf1[c] + ((a0 + a1) + (a2 + a3));
    }
    __syncthreads();
    if (t < 64) {
        float s = 0.f, q = 0.f;
        for (int r = 0; r < 16; r++) { float v = sz[r][t]; s += v; q += v * v; }
        float mu = s * (1.f / Bb), var = q * (1.f / Bb) - mu * mu;
        float inv = rsqrtf(var + 1e-5f);
        float sc = gf1[blockIdx.x * 64 + t] * inv;
        scl[t] = sc; shf[t] = bef1[blockIdx.x * 64 + t] - sc * mu;
    }
    __syncthreads();
    #pragma unroll
    for (int q = 0; q < 4; q++) {
        int r = r0 + q * 4;
        g_fc1[r * 512 + c] = fmaxf(scl[cl] * sz[r][cl] + shf[cl], 0.f);
    }
    if (blockIdx.x == 0)
        for (int i = t; i < 1024; i += 256) out[Bb * NC + i] = se[i];
}

__global__ void __launch_bounds__(256) k_mlp2(
    const float* __restrict__ wf2, const float* __restrict__ bf2,
    const float* __restrict__ gf2, const float* __restrict__ bef2) {
    __shared__ float sf[16 * 512];
    __shared__ float sz[16][32];
    __shared__ float scl[32], shf[32];
    int t = threadIdx.x;
    for (int i = t; i < 8192; i += 256) sf[i] = g_fc1[i];
    __syncthreads();
    int cl = t & 31;
    int r0 = t >> 5;
    int c = blockIdx.x * 32 + cl;
    #pragma unroll
    for (int q = 0; q < 2; q++) {
        int r = r0 + q * 8;
        float a0 = 0.f, a1 = 0.f, a2 = 0.f, a3 = 0.f;
        for (int k = 0; k < 512; k += 4) {
            a0 += sf[r * 512 + k]     * wf2[(k)     * 256 + c];
            a1 += sf[r * 512 + k + 1] * wf2[(k + 1) * 256 + c];
            a2 += sf[r * 512 + k + 2] * wf2[(k + 2) * 256 + c];
            a3 += sf[r * 512 + k + 3] * wf2[(k + 3) * 256 + c];
        }
        sz[r][cl] = bf2[c] + ((a0 + a1) + (a2 + a3));
    }
    __syncthreads();
    if (t < 32) {
        float s = 0.f, q = 0.f;
        for (int r = 0; r < 16; r++) { float v = sz[r][t]; s += v; q += v * v; }
        float mu = s * (1.f / Bb), var = q * (1.f / Bb) - mu * mu;
        float inv = rsqrtf(var + 1e-5f);
        float sc = gf2[blockIdx.x * 32 + t] * inv;
        scl[t] = sc; shf[t] = bef2[blockIdx.x * 32 + t] - sc * mu;
    }
    __syncthreads();
    #pragma unroll
    for (int q = 0; q < 2; q++) {
        int r = r0 + q * 8;
        g_fc2[r * 256 + c] = fmaxf(scl[cl] * sz[r][cl] + shf[cl], 0.f);
    }
}

__global__ void __launch_bounds__(256) k_mlp3(
    const float* __restrict__ wf3, const float* __restrict__ bf3,
    float* __restrict__ out) {
    __shared__ float sf[16 * 256];
    __shared__ float sl[16][11];
    int t = threadIdx.x;
    for (int i = t; i < 4096; i += 256) sf[i] = g_fc2[i];
    __syncthreads();
    if (t < Bb * NC) {
        int r = t / NC, j = t % NC;
        float a0 = 0.f, a1 = 0.f, a2 = 0.f, a3 = 0.f;
        for (int k = 0; k < 256; k += 4) {
            a0 += sf[r * 256 + k]     * wf3[(k)     * NC + j];
            a1 += sf[r * 256 + k + 1] * wf3[(k + 1) * NC + j];
            a2 += sf[r * 256 + k + 2] * wf3[(k + 2) * NC + j];
            a3 += sf[r * 256 + k + 3] * wf3[(k + 3) * NC + j];
        }
        sl[r][j] = bf3[j] + ((a0 + a1) + (a2 + a3));
    }
    __syncthreads();
    if (t < Bb) {
        float m = -1e30f;
        for (int j = 0; j < NC; j++) m = fmaxf(m, sl[t][j]);
        float s = 0.f;
        for (int j = 0; j < NC; j++) s += expf(sl[t][j] - m);
        float l = m + logf(s);
        for (int j = 0; j < NC; j++) out[t * NC + j] = sl[t][j] - l;
    }
}

// ---------------- launcher ----------------
extern "C" void kernel_launch(void* const* d_in, const int* in_sizes, int n_in,
                              void* d_out, int out_size) {
    const float* x      = (const float*)d_in[0];
    const float* ea     = (const float*)d_in[1];
    const float* w_edge = (const float*)d_in[2];
    const float* b_edge = (const float*)d_in[3];
    const float* w1  = (const float*)d_in[4];  const float* b1  = (const float*)d_in[5];
    const float* g1  = (const float*)d_in[6];  const float* be1 = (const float*)d_in[7];
    const float* w2  = (const float*)d_in[8];  const float* b2  = (const float*)d_in[9];
    const float* g2  = (const float*)d_in[10]; const float* be2 = (const float*)d_in[11];
    const float* w3  = (const float*)d_in[12]; const float* b3  = (const float*)d_in[13];
    const float* g3  = (const float*)d_in[14]; const float* be3 = (const float*)d_in[15];
    const float* wf1 = (const float*)d_in[16]; const float* bf1 = (const float*)d_in[17];
    const float* gf1 = (const float*)d_in[18]; const float* bef1= (const float*)d_in[19];
    const float* wf2 = (const float*)d_in[20]; const float* bf2 = (const float*)d_in[21];
    const float* gf2 = (const float*)d_in[22]; const float* bef2= (const float*)d_in[23];
    const float* wf3 = (const float*)d_in[24]; const float* bf3 = (const float*)d_in[25];
    const int*   ei    = (const int*)d_in[26];
    const int*   batch = (const int*)d_in[27];
    float* out = (float*)d_out;

    float *x16, *z1, *z2, *z3, *sum, *sq;
    cudaGetSymbolAddress((void**)&x16, g_x16);
    cudaGetSymbolAddress((void**)&z1,  g_z1);
    cudaGetSymbolAddress((void**)&z2,  g_z2);
    cudaGetSymbolAddress((void**)&z3,  g_z3);
    cudaGetSymbolAddress((void**)&sum, g_sum);
    cudaGetSymbolAddress((void**)&sq,  g_sq);

    const int T = 256;
    k_init<<<(Nn * 16 + T - 1) / T, T>>>(x);
    k_edge<<<(Ee + T - 1) / T, T>>>(ea, w_edge, b_edge, ei);
    k_scan<<<1, 1024>>>();
    k_scatter<<<(Ee + T - 1) / T, T>>>(ei);

    constexpr int LG = 768;  // 768 blocks * 8 warps * 2 rows = 12288
    k_layer<16, FIN, Hh, false, LG><<<LG, T>>>(x16, w1, b1, nullptr, nullptr,
                                               nullptr, nullptr, z1, sum, sq);
    k_layer<Hh, Hh, H2, true, LG><<<LG, T>>>(z1, w2, b2, g1, be1, sum, sq,
                                             z2, sum + 64, sq + 64);
    k_layer<H2, H2, H2, true, LG><<<LG, T>>>(z2, w3, b3, g2, be2, sum + 64, sq + 64,
                                             z3, sum + 128, sq + 128);

    k_pool<<<96, T>>>(z3, batch, g3, be3);

    k_mlp1<<<8, T>>>(wf1, bf1, gf1, bef1, out);
    k_mlp2<<<8, T>>>(wf2, bf2, gf2, bef2);
    k_mlp3<<<1, T>>>(wf3, bf3, out);
}

// round 10
// speedup vs baseline: 1.0487x; 1.0487x over previous
#include <cuda_runtime.h>
#include <math.h>

#define Nn   12288
#define Ee   393216
#define Bb   16
#define FIN  15
#define Hh   32
#define H2   64
#define NC   11

// ---------------- scratch (static device globals; no allocs) ----------------
// invariant: g_cd, g_sum, g_sq, g_emb are ZERO at kernel_launch entry
// (zero-initialized at load; re-zeroed by k_mlp3 tail blocks each run).
__device__ unsigned long long g_cd[Nn];   // [cnt:24 | deg fixed-point 2^-24 : 40]
__device__ float          g_ew[Ee];
__device__ unsigned short g_slot[Ee];
__device__ int            g_rowptr[Nn + 1];
__device__ float          g_dis[Nn];
__device__ float2         g_pack[Ee];     // (col bits, val = ew * dis[col])

__device__ float g_x16[Nn * 16];
__device__ float g_z1[Nn * Hh];
__device__ float g_z2[Nn * H2];
__device__ float g_z3[Nn * H2];

__device__ float g_sum[3 * 64];
__device__ float g_sq [3 * 64];

__device__ float g_emb[Bb * 64];
__device__ float g_fc1[Bb * 512];
__device__ float g_fc2[Bb * 256];

#define FIX_SCALE 16777216.0f
#define FIX_MASK  ((1ull << 40) - 1ull)

// ---------------- edge weights + degree/count (one 64b atomic) + x pad ------
__global__ void k_edge(const float* __restrict__ ea, const float* __restrict__ we,
                       const float* __restrict__ be, const int* __restrict__ ei,
                       const float* __restrict__ x) {
    int e = blockIdx.x * blockDim.x + threadIdx.x;
    if (e < Nn * 16) {             // fold x padding (15 -> 16) into this launch
        int f = e & 15;
        g_x16[e] = (f < FIN) ? x[(e >> 4) * FIN + f] : 0.f;
    }
    if (e >= Ee) return;
    float2 a = ((const float2*)ea)[e];
    float t = a.x * we[0] + a.y * we[1] + be[0];
    float w = 1.f / (1.f + __expf(-t));
    g_ew[e] = w;
    int r = ei[e];
    unsigned long long add = (1ull << 40) | (unsigned long long)(w * FIX_SCALE);
    unsigned long long old = atomicAdd(&g_cd[r], add);
    g_slot[e] = (unsigned short)(old >> 40);   // prior count = this edge's slot
}

// ---- single-block scan of counts -> rowptr; also decode deg -> dis ---------
__global__ void k_scan() {
    __shared__ int warpsum[32];
    __shared__ int warpoff[32];
    int t = threadIdx.x;            // 1024 threads
    const int C = Nn / 1024;        // 12
    int base = t * C;
    int pre[C];
    int s = 0;
    #pragma unroll
    for (int c = 0; c < C; c++) {
        unsigned long long cd = g_cd[base + c];
        int cnt = (int)(cd >> 40);
        float deg = (float)(cd & FIX_MASK) * (1.f / FIX_SCALE);
        g_dis[base + c] = rsqrtf(1.f + deg);
        pre[c] = s; s += cnt;
    }
    int lane = t & 31, wid = t >> 5;
    int v = s;
    #pragma unroll
    for (int o = 1; o < 32; o <<= 1) {
        int n = __shfl_up_sync(0xffffffffu, v, o);
        if (lane >= o) v += n;
    }
    if (lane == 31) warpsum[wid] = v;
    __syncthreads();
    if (wid == 0) {
        int ws = warpsum[lane];
        #pragma unroll
        for (int o = 1; o < 32; o <<= 1) {
            int n = __shfl_up_sync(0xffffffffu, ws, o);
            if (lane >= o) ws += n;
        }
        warpoff[lane] = ws;
    }
    __syncthreads();
    int incl = v + (wid > 0 ? warpoff[wid - 1] : 0);
    int off = incl - s;             // exclusive prefix for this thread's chunk
    #pragma unroll
    for (int c = 0; c < C; c++) g_rowptr[base + c] = off + pre[c];
    if (t == 1023) g_rowptr[Nn] = incl;
}

// ---------------- scatter: NO atomics (slot precomputed) --------------------
__global__ void k_scatter(const int* __restrict__ ei) {
    int e = blockIdx.x * blockDim.x + threadIdx.x;
    if (e >= Ee) return;
    int r = ei[e];
    int c = ei[Ee + e];
    int p = g_rowptr[r] + (int)g_slot[e];
    float val = g_ew[e] * g_dis[c];
    g_pack[p] = make_float2(__int_as_float(c), val);
}

// ---- fused GCN layer: dual-row edge streaming ------------------------------
// Warp u owns rows 2u, 2u+1 whose CSR ranges are contiguous: stream the union
// [sA, eB) in full 32-edge chunks. Each edge routed to accA/accB by predicate.
template <int FI, int FIeff, int FO, bool BN_IN, int GRID>
__global__ void __launch_bounds__(256) k_layer(
    const float* __restrict__ in,
    const float* __restrict__ W,         // [FIeff,FO]
    const float* __restrict__ bias,
    const float* __restrict__ gam, const float* __restrict__ bet,
    const float* __restrict__ sum_in, const float* __restrict__ sq_in,
    float* __restrict__ out,
    float* __restrict__ sum_out, float* __restrict__ sq_out)
{
    constexpr int LPE = FI / 4;
    constexpr int EPW = 32 / LPE;        // 2 (FI=64), 4 (FI=32), 8 (FI=16)
    __shared__ float  sW[FIeff * FO];
    __shared__ float4 sRowA[8][16];
    __shared__ float4 sRowB[8][16];
    __shared__ float  sScale[FI], sShift[FI];
    __shared__ float  sSum[FO], sSq[FO];
    int tid = threadIdx.x;
    for (int i = tid; i < FIeff * FO; i += 256) sW[i] = W[i];
    if (tid < FO) { sSum[tid] = 0.f; sSq[tid] = 0.f; }
    if (tid < FI) {
        if (BN_IN) {
            float mu  = sum_in[tid] * (1.f / (float)Nn);
            float var = sq_in[tid]  * (1.f / (float)Nn) - mu * mu;
            float inv = rsqrtf(var + 1e-5f);
            float sc  = gam[tid] * inv;
            sScale[tid] = sc;
            sShift[tid] = bet[tid] - sc * mu;
        } else { sScale[tid] = 1.f; sShift[tid] = 0.f; }
    }
    __syncthreads();

    int warp = tid >> 5, lane = tid & 31;
    int eh = lane / LPE;        // edge slot
    int fl = lane % LPE;        // feature quad
    float4 sc4, sh4;
    sc4.x = sScale[4*fl+0]; sc4.y = sScale[4*fl+1];
    sc4.z = sScale[4*fl+2]; sc4.w = sScale[4*fl+3];
    sh4.x = sShift[4*fl+0]; sh4.y = sShift[4*fl+1];
    sh4.z = sShift[4*fl+2]; sh4.w = sShift[4*fl+3];
    float b0 = (lane < FO) ? bias[lane] : 0.f;
    float b1 = (FO > 32) ? bias[lane + 32] : 0.f;

    const float4* in4 = (const float4*)in;
    int u  = blockIdx.x * 8 + warp;      // GRID*8 == 6144 warps
    int rA = 2 * u, rB = rA + 1;
    float dA = g_dis[rA], dB = g_dis[rB];
    int sA = g_rowptr[rA], eA = g_rowptr[rA + 1], eB = g_rowptr[rA + 2];

    float4 accA = make_float4(0.f, 0.f, 0.f, 0.f);
    float4 accB = make_float4(0.f, 0.f, 0.f, 0.f);
    if (eh == 0) {   // self-loop row A
        float4 v = in4[rA * LPE + fl];
        if (BN_IN) {
            v.x = fmaxf(fmaf(sc4.x, v.x, sh4.x), 0.f);
            v.y = fmaxf(fmaf(sc4.y, v.y, sh4.y), 0.f);
            v.z = fmaxf(fmaf(sc4.z, v.z, sh4.z), 0.f);
            v.w = fmaxf(fmaf(sc4.w, v.w, sh4.w), 0.f);
        }
        accA.x = dA * v.x; accA.y = dA * v.y; accA.z = dA * v.z; accA.w = dA * v.w;
    } else if (eh == 1) {   // self-loop row B
        float4 v = in4[rB * LPE + fl];
        if (BN_IN) {
            v.x = fmaxf(fmaf(sc4.x, v.x, sh4.x), 0.f);
            v.y = fmaxf(fmaf(sc4.y, v.y, sh4.y), 0.f);
            v.z = fmaxf(fmaf(sc4.z, v.z, sh4.z), 0.f);
            v.w = fmaxf(fmaf(sc4.w, v.w, sh4.w), 0.f);
        }
        accB.x = dB * v.x; accB.y = dB * v.y; accB.z = dB * v.z; accB.w = dB * v.w;
    }

    for (int k = sA; k < eB; k += 32) {
        float2 pk = (k + lane < eB) ? __ldg(&g_pack[k + lane])
                                    : make_float2(__int_as_float(0), 0.f);
        #pragma unroll
        for (int j = 0; j < 32; j += EPW) {
            int   c = __float_as_int(__shfl_sync(0xffffffffu, pk.x, j + eh));
            float w = __shfl_sync(0xffffffffu, pk.y, j + eh);
            float4 v = in4[c * LPE + fl];
            if (BN_IN) {
                v.x = fmaxf(fmaf(sc4.x, v.x, sh4.x), 0.f);
                v.y = fmaxf(fmaf(sc4.y, v.y, sh4.y), 0.f);
                v.z = fmaxf(fmaf(sc4.z, v.z, sh4.z), 0.f);
                v.w = fmaxf(fmaf(sc4.w, v.w, sh4.w), 0.f);
            }
            bool isA = (k + j + eh) < eA;
            float wA = isA ? w : 0.f;
            float wB = isA ? 0.f : w;
            accA.x = fmaf(wA, v.x, accA.x);
            accA.y = fmaf(wA, v.y, accA.y);
            accA.z = fmaf(wA, v.z, accA.z);
            accA.w = fmaf(wA, v.w, accA.w);
            accB.x = fmaf(wB, v.x, accB.x);
            accB.y = fmaf(wB, v.y, accB.y);
            accB.z = fmaf(wB, v.z, accB.z);
            accB.w = fmaf(wB, v.w, accB.w);
        }
    }
    // reduce over edge slots (every lane ends with totals for its quad)
    #pragma unroll
    for (int o = LPE; o < 32; o <<= 1) {
        accA.x += __shfl_xor_sync(0xffffffffu, accA.x, o);
        accA.y += __shfl_xor_sync(0xffffffffu, accA.y, o);
        accA.z += __shfl_xor_sync(0xffffffffu, accA.z, o);
        accA.w += __shfl_xor_sync(0xffffffffu, accA.w, o);
        accB.x += __shfl_xor_sync(0xffffffffu, accB.x, o);
        accB.y += __shfl_xor_sync(0xffffffffu, accB.y, o);
        accB.z += __shfl_xor_sync(0xffffffffu, accB.z, o);
        accB.w += __shfl_xor_sync(0xffffffffu, accB.w, o);
    }
    accA.x *= dA; accA.y *= dA; accA.z *= dA; accA.w *= dA;
    accB.x *= dB; accB.y *= dB; accB.z *= dB; accB.w *= dB;
    if (eh == 0) sRowA[warp][fl] = accA;
    if (eh == 1) sRowB[warp][fl] = accB;
    __syncwarp();

    // GEMM for both rows; W-column loads shared
    const float* hA = (const float*)&sRowA[warp][0];
    const float* hB = (const float*)&sRowB[warp][0];
    float oA0 = b0, oA1 = b1, oB0 = b0, oB1 = b1;
    #pragma unroll
    for (int f = 0; f < FIeff; f++) {
        float ha = hA[f], hb = hB[f];
        float wv0 = sW[f * FO + lane];
        oA0 = fmaf(ha, wv0, oA0);
        oB0 = fmaf(hb, wv0, oB0);
        if (FO > 32) {
            float wv1 = sW[f * FO + lane + 32];
            oA1 = fmaf(ha, wv1, oA1);
            oB1 = fmaf(hb, wv1, oB1);
        }
    }
    if (lane < FO) {
        out[rA * FO + lane] = oA0;
        out[rB * FO + lane] = oB0;
        atomicAdd(&sSum[lane], oA0 + oB0);
        atomicAdd(&sSq[lane],  oA0 * oA0 + oB0 * oB0);
    }
    if (FO > 32) {
        out[rA * FO + lane + 32] = oA1;
        out[rB * FO + lane + 32] = oB1;
        atomicAdd(&sSum[lane + 32], oA1 + oB1);
        atomicAdd(&sSq[lane + 32],  oA1 * oA1 + oB1 * oB1);
    }
    __syncthreads();
    if (tid < FO) {
        atomicAdd(&sum_out[tid], sSum[tid]);
        atomicAdd(&sq_out[tid],  sSq[tid]);
    }
}

// ---------------- max pool: sorted-batch segment flush ----------------------
__global__ void __launch_bounds__(256) k_pool(
    const float* __restrict__ z3, const int* __restrict__ batch,
    const float* __restrict__ gam, const float* __restrict__ bet) {
    __shared__ float scl[64], shf[64];
    int t = threadIdx.x;
    if (t < 64) {
        float mu  = g_sum[128 + t] * (1.f / (float)Nn);
        float var = g_sq [128 + t] * (1.f / (float)Nn) - mu * mu;
        float inv = rsqrtf(var + 1e-5f);
        float sc  = gam[t] * inv;
        scl[t] = sc; shf[t] = bet[t] - sc * mu;
    }
    __syncthreads();
    int f  = t & 63;
    int r0 = blockIdx.x * 128 + (t >> 6);
    float sc = scl[f], sh = shf[f];
    int curb = -1; float cm = 0.f;
    for (int r = r0; r < blockIdx.x * 128 + 128; r += 4) {
        int b = batch[r];
        float v = fmaxf(fmaf(sc, z3[r * 64 + f], sh), 0.f);
        if (b != curb) {
            if (curb >= 0) atomicMax((int*)&g_emb[curb * 64 + f], __float_as_int(cm));
            curb = b; cm = v;
        } else cm = fmaxf(cm, v);
    }
    if (curb >= 0) atomicMax((int*)&g_emb[curb * 64 + f], __float_as_int(cm));
}

// ---------------- MLP head --------------------------------------------------
__global__ void __launch_bounds__(256) k_mlp1(
    const float* __restrict__ wf1, const float* __restrict__ bf1,
    const float* __restrict__ gf1, const float* __restrict__ bef1,
    float* __restrict__ out) {
    __shared__ float se[16 * 64];
    __shared__ float sz[16][64];
    __shared__ float scl[64], shf[64];
    int t = threadIdx.x;
    for (int i = t; i < 1024; i += 256) se[i] = g_emb[i];
    __syncthreads();
    int cl = t & 63;
    int r0 = t >> 6;
    int c = blockIdx.x * 64 + cl;
    #pragma unroll
    for (int q = 0; q < 4; q++) {
        int r = r0 + q * 4;
        float a0 = 0.f, a1 = 0.f, a2 = 0.f, a3 = 0.f;
        #pragma unroll
        for (int k = 0; k < 64; k += 4) {
            a0 += se[r * 64 + k]     * wf1[(k)     * 512 + c];
            a1 += se[r * 64 + k + 1] * wf1[(k + 1) * 512 + c];
            a2 += se[r * 64 + k + 2] * wf1[(k + 2) * 512 + c];
            a3 += se[r * 64 + k + 3] * wf1[(k + 3) * 512 + c];
        }
        sz[r][cl] = bf1[c] + ((a0 + a1) + (a2 + a3));
    }
    __syncthreads();
    if (t < 64) {
        float s = 0.f, q = 0.f;
        for (int r = 0; r < 16; r++) { float v = sz[r][t]; s += v; q += v * v; }
        float mu = s * (1.f / Bb), var = q * (1.f / Bb) - mu * mu;
        float inv = rsqrtf(var + 1e-5f);
        float sc = gf1[blockIdx.x * 64 + t] * inv;
        scl[t] = sc; shf[t] = bef1[blockIdx.x * 64 + t] - sc * mu;
    }
    __syncthreads();
    #pragma unroll
    for (int q = 0; q < 4; q++) {
        int r = r0 + q * 4;
        g_fc1[r * 512 + c] = fmaxf(scl[cl] * sz[r][cl] + shf[cl], 0.f);
    }
    if (blockIdx.x == 0)
        for (int i = t; i < 1024; i += 256) out[Bb * NC + i] = se[i];
}

__global__ void __launch_bounds__(256) k_mlp2(
    const float* __restrict__ wf2, const float* __restrict__ bf2,
    const float* __restrict__ gf2, const float* __restrict__ bef2) {
    __shared__ float sf[16 * 512];
    __shared__ float sz[16][32];
    __shared__ float scl[32], shf[32];
    int t = threadIdx.x;
    for (int i = t; i < 8192; i += 256) sf[i] = g_fc1[i];
    __syncthreads();
    int cl = t & 31;
    int r0 = t >> 5;
    int c = blockIdx.x * 32 + cl;
    #pragma unroll
    for (int q = 0; q < 2; q++) {
        int r = r0 + q * 8;
        float a0 = 0.f, a1 = 0.f, a2 = 0.f, a3 = 0.f;
        for (int k = 0; k < 512; k += 4) {
            a0 += sf[r * 512 + k]     * wf2[(k)     * 256 + c];
            a1 += sf[r * 512 + k + 1] * wf2[(k + 1) * 256 + c];
            a2 += sf[r * 512 + k + 2] * wf2[(k + 2) * 256 + c];
            a3 += sf[r * 512 + k + 3] * wf2[(k + 3) * 256 + c];
        }
        sz[r][cl] = bf2[c] + ((a0 + a1) + (a2 + a3));
    }
    __syncthreads();
    if (t < 32) {
        float s = 0.f, q = 0.f;
        for (int r = 0; r < 16; r++) { float v = sz[r][t]; s += v; q += v * v; }
        float mu = s * (1.f / Bb), var = q * (1.f / Bb) - mu * mu;
        float inv = rsqrtf(var + 1e-5f);
        float sc = gf2[blockIdx.x * 32 + t] * inv;
        scl[t] = sc; shf[t] = bef2[blockIdx.x * 32 + t] - sc * mu;
    }
    __syncthreads();
    #pragma unroll
    for (int q = 0; q < 2; q++) {
        int r = r0 + q * 8;
        g_fc2[r * 256 + c] = fmaxf(scl[cl] * sz[r][cl] + shf[cl], 0.f);
    }
}

// block 0: fc3 + log_softmax.  blocks 1..4: zero counters for next run.
__global__ void __launch_bounds__(256) k_mlp3(
    const float* __restrict__ wf3, const float* __restrict__ bf3,
    float* __restrict__ out) {
    int t = threadIdx.x;
    if (blockIdx.x > 0) {
        int g = (blockIdx.x - 1) * 256 + t;        // 1024 threads
        for (int i = g; i < Nn; i += 1024) g_cd[i] = 0ull;
        if (g < 192) { g_sum[g] = 0.f; g_sq[g] = 0.f; }
        g_emb[g] = 0.f;                            // 1024 elements exactly
        return;
    }
    __shared__ float sf[16 * 256];
    __shared__ float sl[16][11];
    for (int i = t; i < 4096; i += 256) sf[i] = g_fc2[i];
    __syncthreads();
    if (t < Bb * NC) {
        int r = t / NC, j = t % NC;
        float a0 = 0.f, a1 = 0.f, a2 = 0.f, a3 = 0.f;
        for (int k = 0; k < 256; k += 4) {
            a0 += sf[r * 256 + k]     * wf3[(k)     * NC + j];
            a1 += sf[r * 256 + k + 1] * wf3[(k + 1) * NC + j];
            a2 += sf[r * 256 + k + 2] * wf3[(k + 2) * NC + j];
            a3 += sf[r * 256 + k + 3] * wf3[(k + 3) * NC + j];
        }
        sl[r][j] = bf3[j] + ((a0 + a1) + (a2 + a3));
    }
    __syncthreads();
    if (t < Bb) {
        float m = -1e30f;
        for (int j = 0; j < NC; j++) m = fmaxf(m, sl[t][j]);
        float s = 0.f;
        for (int j = 0; j < NC; j++) s += expf(sl[t][j] - m);
        float l = m + logf(s);
        for (int j = 0; j < NC; j++) out[t * NC + j] = sl[t][j] - l;
    }
}

// ---------------- launcher ----------------
extern "C" void kernel_launch(void* const* d_in, const int* in_sizes, int n_in,
                              void* d_out, int out_size) {
    const float* x      = (const float*)d_in[0];
    const float* ea     = (const float*)d_in[1];
    const float* w_edge = (const float*)d_in[2];
    const float* b_edge = (const float*)d_in[3];
    const float* w1  = (const float*)d_in[4];  const float* b1  = (const float*)d_in[5];
    const float* g1  = (const float*)d_in[6];  const float* be1 = (const float*)d_in[7];
    const float* w2  = (const float*)d_in[8];  const float* b2  = (const float*)d_in[9];
    const float* g2  = (const float*)d_in[10]; const float* be2 = (const float*)d_in[11];
    const float* w3  = (const float*)d_in[12]; const float* b3  = (const float*)d_in[13];
    const float* g3  = (const float*)d_in[14]; const float* be3 = (const float*)d_in[15];
    const float* wf1 = (const float*)d_in[16]; const float* bf1 = (const float*)d_in[17];
    const float* gf1 = (const float*)d_in[18]; const float* bef1= (const float*)d_in[19];
    const float* wf2 = (const float*)d_in[20]; const float* bf2 = (const float*)d_in[21];
    const float* gf2 = (const float*)d_in[22]; const float* bef2= (const float*)d_in[23];
    const float* wf3 = (const float*)d_in[24]; const float* bf3 = (const float*)d_in[25];
    const int*   ei    = (const int*)d_in[26];
    const int*   batch = (const int*)d_in[27];
    float* out = (float*)d_out;

    float *x16, *z1, *z2, *z3, *sum, *sq;
    cudaGetSymbolAddress((void**)&x16, g_x16);
    cudaGetSymbolAddress((void**)&z1,  g_z1);
    cudaGetSymbolAddress((void**)&z2,  g_z2);
    cudaGetSymbolAddress((void**)&z3,  g_z3);
    cudaGetSymbolAddress((void**)&sum, g_sum);
    cudaGetSymbolAddress((void**)&sq,  g_sq);

    const int T = 256;
    k_edge<<<(Ee + T - 1) / T, T>>>(ea, w_edge, b_edge, ei, x);
    k_scan<<<1, 1024>>>();
    k_scatter<<<(Ee + T - 1) / T, T>>>(ei);

    constexpr int LG = 768;  // 768 blocks * 8 warps; each warp streams 2 rows
    k_layer<16, FIN, Hh, false, LG><<<LG, T>>>(x16, w1, b1, nullptr, nullptr,
                                               nullptr, nullptr, z1, sum, sq);
    k_layer<Hh, Hh, H2, true, LG><<<LG, T>>>(z1, w2, b2, g1, be1, sum, sq,
                                             z2, sum + 64, sq + 64);
    k_layer<H2, H2, H2, true, LG><<<LG, T>>>(z2, w3, b3, g2, be2, sum + 64, sq + 64,
                                             z3, sum + 128, sq + 128);

    k_pool<<<96, T>>>(z3, batch, g3, be3);

    k_mlp1<<<8, T>>>(wf1, bf1, gf1, bef1, out);
    k_mlp2<<<8, T>>>(wf2, bf2, gf2, bef2);
    k_mlp3<<<5, T>>>(wf3, bf3, out);
}

// round 11
// speedup vs baseline: 1.0703x; 1.0206x over previous
#include <cuda_runtime.h>
#include <math.h>

#define Nn   12288
#define Ee   393216
#define Bb   16
#define FIN  15
#define Hh   32
#define H2   64
#define NC   11

// ---------------- scratch (static device globals; no allocs) ----------------
// invariant: g_cd, g_sum, g_sq, g_emb are ZERO at kernel_launch entry
// (zero-initialized at load; re-zeroed by k_mlp3 tail blocks each run).
__device__ unsigned long long g_cd[Nn];   // [cnt:24 | deg fixed-point 2^-24 : 40]
__device__ float          g_ew[Ee];
__device__ unsigned short g_slot[Ee];
__device__ int            g_rowptr[Nn + 1];
__device__ float          g_dis[Nn];
__device__ float2         g_pack[Ee];     // (col bits, val = ew * dis[col])

__device__ float g_x16[Nn * 16];
__device__ float g_z1[Nn * Hh];
__device__ float g_z2[Nn * H2];
__device__ float g_z3[Nn * H2];

__device__ float g_sum[3 * 64];
__device__ float g_sq [3 * 64];

__device__ float g_emb[Bb * 64];
__device__ float g_fc1[Bb * 512];
__device__ float g_fc2[Bb * 256];

#define FIX_SCALE 16777216.0f
#define FIX_MASK  ((1ull << 40) - 1ull)

// ---------------- edge weights + degree/count (one 64b atomic) + x pad ------
__global__ void k_edge(const float* __restrict__ ea, const float* __restrict__ we,
                       const float* __restrict__ be, const int* __restrict__ ei,
                       const float* __restrict__ x) {
    int e = blockIdx.x * blockDim.x + threadIdx.x;
    if (e < Nn * 16) {             // fold x padding (15 -> 16) into this launch
        int f = e & 15;
        g_x16[e] = (f < FIN) ? x[(e >> 4) * FIN + f] : 0.f;
    }
    if (e >= Ee) return;
    float2 a = ((const float2*)ea)[e];
    float t = a.x * we[0] + a.y * we[1] + be[0];
    float w = 1.f / (1.f + __expf(-t));
    g_ew[e] = w;
    int r = ei[e];
    unsigned long long add = (1ull << 40) | (unsigned long long)(w * FIX_SCALE);
    unsigned long long old = atomicAdd(&g_cd[r], add);
    g_slot[e] = (unsigned short)(old >> 40);   // prior count = this edge's slot
}

// ---- single-block scan of counts -> rowptr; also decode deg -> dis ---------
__global__ void k_scan() {
    __shared__ int warpsum[32];
    __shared__ int warpoff[32];
    int t = threadIdx.x;            // 1024 threads
    const int C = Nn / 1024;        // 12
    int base = t * C;
    int pre[C];
    int s = 0;
    #pragma unroll
    for (int c = 0; c < C; c++) {
        unsigned long long cd = g_cd[base + c];
        int cnt = (int)(cd >> 40);
        float deg = (float)(cd & FIX_MASK) * (1.f / FIX_SCALE);
        g_dis[base + c] = rsqrtf(1.f + deg);
        pre[c] = s; s += cnt;
    }
    int lane = t & 31, wid = t >> 5;
    int v = s;
    #pragma unroll
    for (int o = 1; o < 32; o <<= 1) {
        int n = __shfl_up_sync(0xffffffffu, v, o);
        if (lane >= o) v += n;
    }
    if (lane == 31) warpsum[wid] = v;
    __syncthreads();
    if (wid == 0) {
        int ws = warpsum[lane];
        #pragma unroll
        for (int o = 1; o < 32; o <<= 1) {
            int n = __shfl_up_sync(0xffffffffu, ws, o);
            if (lane >= o) ws += n;
        }
        warpoff[lane] = ws;
    }
    __syncthreads();
    int incl = v + (wid > 0 ? warpoff[wid - 1] : 0);
    int off = incl - s;
    #pragma unroll
    for (int c = 0; c < C; c++) g_rowptr[base + c] = off + pre[c];
    if (t == 1023) g_rowptr[Nn] = incl;
}

// ---------------- scatter: NO atomics (slot precomputed) --------------------
__global__ void k_scatter(const int* __restrict__ ei) {
    int e = blockIdx.x * blockDim.x + threadIdx.x;
    if (e >= Ee) return;
    int r = ei[e];
    int c = ei[Ee + e];
    int p = g_rowptr[r] + (int)g_slot[e];
    float val = g_ew[e] * g_dis[c];
    g_pack[p] = make_float2(__int_as_float(c), val);
}

// ---- fused GCN layer: SpMM (normalized input) -> GEMM -> BN stats ----------
// Warp u owns rows 2u, 2u+1 (contiguous CSR union). Lane-groups of LPE lanes
// each stream their own edges directly (broadcast pack loads, NO shuffles),
// unrolled x2. Edge routed to accA/accB by predicate.
template <int FI, int FIeff, int FO, int GRID>
__global__ void __launch_bounds__(256) k_layer(
    const float* __restrict__ in,        // [N,FI] already BN+ReLU'd (or raw x)
    const float* __restrict__ W,         // [FIeff,FO]
    const float* __restrict__ bias,
    float* __restrict__ out,             // [N,FO] raw
    float* __restrict__ sum_out, float* __restrict__ sq_out)
{
    constexpr int LPE = FI / 4;
    constexpr int EPW = 32 / LPE;        // 2 (FI=64), 4 (FI=32), 8 (FI=16)
    __shared__ float  sW[FIeff * FO];
    __shared__ float4 sRowA[8][16];
    __shared__ float4 sRowB[8][16];
    __shared__ float  sSum[FO], sSq[FO];
    int tid = threadIdx.x;
    for (int i = tid; i < FIeff * FO; i += 256) sW[i] = W[i];
    if (tid < FO) { sSum[tid] = 0.f; sSq[tid] = 0.f; }
    __syncthreads();

    int warp = tid >> 5, lane = tid & 31;
    int eh = lane / LPE;        // edge-group id
    int fl = lane % LPE;        // feature quad
    float b0 = (lane < FO) ? bias[lane] : 0.f;
    float b1 = (FO > 32) ? bias[lane + 32] : 0.f;

    const float4* in4 = (const float4*)in;
    int u  = blockIdx.x * 8 + warp;      // GRID*8 == 6144 warps
    int rA = 2 * u, rB = rA + 1;
    float dA = g_dis[rA], dB = g_dis[rB];
    int sA = g_rowptr[rA], eA = g_rowptr[rA + 1], eB = g_rowptr[rA + 2];

    float4 accA = make_float4(0.f, 0.f, 0.f, 0.f);
    float4 accB = make_float4(0.f, 0.f, 0.f, 0.f);
    if (eh == 0) {   // self-loop row A (weight 1)
        float4 v = in4[rA * LPE + fl];
        accA.x = dA * v.x; accA.y = dA * v.y; accA.z = dA * v.z; accA.w = dA * v.w;
    } else if (eh == 1) {   // self-loop row B
        float4 v = in4[rB * LPE + fl];
        accB.x = dB * v.x; accB.y = dB * v.y; accB.z = dB * v.z; accB.w = dB * v.w;
    }

    // direct per-group edge stream, unrolled x2, no shuffles
    int k = sA + eh;
    for (; k + EPW < eB; k += 2 * EPW) {
        float2 p0 = __ldg(&g_pack[k]);
        float2 p1 = __ldg(&g_pack[k + EPW]);
        int c0 = __float_as_int(p0.x);
        int c1 = __float_as_int(p1.x);
        float4 v0 = in4[c0 * LPE + fl];
        float4 v1 = in4[c1 * LPE + fl];
        bool a0 = k < eA, a1 = (k + EPW) < eA;
        float wA0 = a0 ? p0.y : 0.f, wB0 = a0 ? 0.f : p0.y;
        float wA1 = a1 ? p1.y : 0.f, wB1 = a1 ? 0.f : p1.y;
        accA.x = fmaf(wA0, v0.x, accA.x); accB.x = fmaf(wB0, v0.x, accB.x);
        accA.y = fmaf(wA0, v0.y, accA.y); accB.y = fmaf(wB0, v0.y, accB.y);
        accA.z = fmaf(wA0, v0.z, accA.z); accB.z = fmaf(wB0, v0.z, accB.z);
        accA.w = fmaf(wA0, v0.w, accA.w); accB.w = fmaf(wB0, v0.w, accB.w);
        accA.x = fmaf(wA1, v1.x, accA.x); accB.x = fmaf(wB1, v1.x, accB.x);
        accA.y = fmaf(wA1, v1.y, accA.y); accB.y = fmaf(wB1, v1.y, accB.y);
        accA.z = fmaf(wA1, v1.z, accA.z); accB.z = fmaf(wB1, v1.z, accB.z);
        accA.w = fmaf(wA1, v1.w, accA.w); accB.w = fmaf(wB1, v1.w, accB.w);
    }
    if (k < eB) {
        float2 p0 = __ldg(&g_pack[k]);
        int c0 = __float_as_int(p0.x);
        float4 v0 = in4[c0 * LPE + fl];
        bool a0 = k < eA;
        float wA0 = a0 ? p0.y : 0.f, wB0 = a0 ? 0.f : p0.y;
        accA.x = fmaf(wA0, v0.x, accA.x); accB.x = fmaf(wB0, v0.x, accB.x);
        accA.y = fmaf(wA0, v0.y, accA.y); accB.y = fmaf(wB0, v0.y, accB.y);
        accA.z = fmaf(wA0, v0.z, accA.z); accB.z = fmaf(wB0, v0.z, accB.z);
        accA.w = fmaf(wA0, v0.w, accA.w); accB.w = fmaf(wB0, v0.w, accB.w);
    }

    // reduce over edge groups
    #pragma unroll
    for (int o = LPE; o < 32; o <<= 1) {
        accA.x += __shfl_xor_sync(0xffffffffu, accA.x, o);
        accA.y += __shfl_xor_sync(0xffffffffu, accA.y, o);
        accA.z += __shfl_xor_sync(0xffffffffu, accA.z, o);
        accA.w += __shfl_xor_sync(0xffffffffu, accA.w, o);
        accB.x += __shfl_xor_sync(0xffffffffu, accB.x, o);
        accB.y += __shfl_xor_sync(0xffffffffu, accB.y, o);
        accB.z += __shfl_xor_sync(0xffffffffu, accB.z, o);
        accB.w += __shfl_xor_sync(0xffffffffu, accB.w, o);
    }
    accA.x *= dA; accA.y *= dA; accA.z *= dA; accA.w *= dA;
    accB.x *= dB; accB.y *= dB; accB.z *= dB; accB.w *= dB;
    if (eh == 0) sRowA[warp][fl] = accA;
    if (eh == 1) sRowB[warp][fl] = accB;
    __syncwarp();

    // GEMM for both rows; W-column loads shared
    const float* hA = (const float*)&sRowA[warp][0];
    const float* hB = (const float*)&sRowB[warp][0];
    float oA0 = b0, oA1 = b1, oB0 = b0, oB1 = b1;
    #pragma unroll
    for (int f = 0; f < FIeff; f++) {
        float ha = hA[f], hb = hB[f];
        float wv0 = sW[f * FO + lane];
        oA0 = fmaf(ha, wv0, oA0);
        oB0 = fmaf(hb, wv0, oB0);
        if (FO > 32) {
            float wv1 = sW[f * FO + lane + 32];
            oA1 = fmaf(ha, wv1, oA1);
            oB1 = fmaf(hb, wv1, oB1);
        }
    }
    if (lane < FO) {
        out[rA * FO + lane] = oA0;
        out[rB * FO + lane] = oB0;
        atomicAdd(&sSum[lane], oA0 + oB0);
        atomicAdd(&sSq[lane],  oA0 * oA0 + oB0 * oB0);
    }
    if (FO > 32) {
        out[rA * FO + lane + 32] = oA1;
        out[rB * FO + lane + 32] = oB1;
        atomicAdd(&sSum[lane + 32], oA1 + oB1);
        atomicAdd(&sSq[lane + 32],  oA1 * oA1 + oB1 * oB1);
    }
    __syncthreads();
    if (tid < FO) {
        atomicAdd(&sum_out[tid], sSum[tid]);
        atomicAdd(&sq_out[tid],  sSq[tid]);
    }
}

// ---------------- in-place BN + ReLU (vectorized) ---------------------------
template <int F>
__global__ void __launch_bounds__(256) k_norm(
    float* __restrict__ z,
    const float* __restrict__ gam, const float* __restrict__ bet,
    const float* __restrict__ sum, const float* __restrict__ sq) {
    __shared__ float scl[F], shf[F];
    int t = threadIdx.x;
    if (t < F) {
        float mu  = sum[t] * (1.f / (float)Nn);
        float var = sq[t]  * (1.f / (float)Nn) - mu * mu;
        float inv = rsqrtf(var + 1e-5f);
        float sc  = gam[t] * inv;
        scl[t] = sc; shf[t] = bet[t] - sc * mu;
    }
    __syncthreads();
    int idx = blockIdx.x * 256 + t;          // float4 index; grid sized exactly
    float4 v = ((float4*)z)[idx];
    int f = (idx * 4) & (F - 1);             // F is a power of two
    v.x = fmaxf(fmaf(scl[f],     v.x, shf[f]),     0.f);
    v.y = fmaxf(fmaf(scl[f + 1], v.y, shf[f + 1]), 0.f);
    v.z = fmaxf(fmaf(scl[f + 2], v.z, shf[f + 2]), 0.f);
    v.w = fmaxf(fmaf(scl[f + 3], v.w, shf[f + 3]), 0.f);
    ((float4*)z)[idx] = v;
}

// ---------------- max pool: sorted-batch segment flush (BN3 inline) ---------
__global__ void __launch_bounds__(256) k_pool(
    const float* __restrict__ z3, const int* __restrict__ batch,
    const float* __restrict__ gam, const float* __restrict__ bet) {
    __shared__ float scl[64], shf[64];
    int t = threadIdx.x;
    if (t < 64) {
        float mu  = g_sum[128 + t] * (1.f / (float)Nn);
        float var = g_sq [128 + t] * (1.f / (float)Nn) - mu * mu;
        float inv = rsqrtf(var + 1e-5f);
        float sc  = gam[t] * inv;
        scl[t] = sc; shf[t] = bet[t] - sc * mu;
    }
    __syncthreads();
    int f  = t & 63;
    int r0 = blockIdx.x * 128 + (t >> 6);
    float sc = scl[f], sh = shf[f];
    int curb = -1; float cm = 0.f;
    for (int r = r0; r < blockIdx.x * 128 + 128; r += 4) {
        int b = batch[r];
        float v = fmaxf(fmaf(sc, z3[r * 64 + f], sh), 0.f);
        if (b != curb) {
            if (curb >= 0) atomicMax((int*)&g_emb[curb * 64 + f], __float_as_int(cm));
            curb = b; cm = v;
        } else cm = fmaxf(cm, v);
    }
    if (curb >= 0) atomicMax((int*)&g_emb[curb * 64 + f], __float_as_int(cm));
}

// ---------------- MLP head --------------------------------------------------
__global__ void __launch_bounds__(256) k_mlp1(
    const float* __restrict__ wf1, const float* __restrict__ bf1,
    const float* __restrict__ gf1, const float* __restrict__ bef1,
    float* __restrict__ out) {
    __shared__ float se[16 * 64];
    __shared__ float sz[16][64];
    __shared__ float scl[64], shf[64];
    int t = threadIdx.x;
    for (int i = t; i < 1024; i += 256) se[i] = g_emb[i];
    __syncthreads();
    int cl = t & 63;
    int r0 = t >> 6;
    int c = blockIdx.x * 64 + cl;
    #pragma unroll
    for (int q = 0; q < 4; q++) {
        int r = r0 + q * 4;
        float a0 = 0.f, a1 = 0.f, a2 = 0.f, a3 = 0.f;
        #pragma unroll
        for (int k = 0; k < 64; k += 4) {
            a0 += se[r * 64 + k]     * wf1[(k)     * 512 + c];
            a1 += se[r * 64 + k + 1] * wf1[(k + 1) * 512 + c];
            a2 += se[r * 64 + k + 2] * wf1[(k + 2) * 512 + c];
            a3 += se[r * 64 + k + 3] * wf1[(k + 3) * 512 + c];
        }
        sz[r][cl] = bf1[c] + ((a0 + a1) + (a2 + a3));
    }
    __syncthreads();
    if (t < 64) {
        float s = 0.f, q = 0.f;
        for (int r = 0; r < 16; r++) { float v = sz[r][t]; s += v; q += v * v; }
        float mu = s * (1.f / Bb), var = q * (1.f / Bb) - mu * mu;
        float inv = rsqrtf(var + 1e-5f);
        float sc = gf1[blockIdx.x * 64 + t] * inv;
        scl[t] = sc; shf[t] = bef1[blockIdx.x * 64 + t] - sc * mu;
    }
    __syncthreads();
    #pragma unroll
    for (int q = 0; q < 4; q++) {
        int r = r0 + q * 4;
        g_fc1[r * 512 + c] = fmaxf(scl[cl] * sz[r][cl] + shf[cl], 0.f);
    }
    if (blockIdx.x == 0)
        for (int i = t; i < 1024; i += 256) out[Bb * NC + i] = se[i];
}

__global__ void __launch_bounds__(256) k_mlp2(
    const float* __restrict__ wf2, const float* __restrict__ bf2,
    const float* __restrict__ gf2, const float* __restrict__ bef2) {
    __shared__ float sf[16 * 512];
    __shared__ float sz[16][32];
    __shared__ float scl[32], shf[32];
    int t = threadIdx.x;
    for (int i = t; i < 8192; i += 256) sf[i] = g_fc1[i];
    __syncthreads();
    int cl = t & 31;
    int r0 = t >> 5;
    int c = blockIdx.x * 32 + cl;
    #pragma unroll
    for (int q = 0; q < 2; q++) {
        int r = r0 + q * 8;
        float a0 = 0.f, a1 = 0.f, a2 = 0.f, a3 = 0.f;
        for (int k = 0; k < 512; k += 4) {
            a0 += sf[r * 512 + k]     * wf2[(k)     * 256 + c];
            a1 += sf[r * 512 + k + 1] * wf2[(k + 1) * 256 + c];
            a2 += sf[r * 512 + k + 2] * wf2[(k + 2) * 256 + c];
            a3 += sf[r * 512 + k + 3] * wf2[(k + 3) * 256 + c];
        }
        sz[r][cl] = bf2[c] + ((a0 + a1) + (a2 + a3));
    }
    __syncthreads();
    if (t < 32) {
        float s = 0.f, q = 0.f;
        for (int r = 0; r < 16; r++) { float v = sz[r][t]; s += v; q += v * v; }
        float mu = s * (1.f / Bb), var = q * (1.f / Bb) - mu * mu;
        float inv = rsqrtf(var + 1e-5f);
        float sc = gf2[blockIdx.x * 32 + t] * inv;
        scl[t] = sc; shf[t] = bef2[blockIdx.x * 32 + t] - sc * mu;
    }
    __syncthreads();
    #pragma unroll
    for (int q = 0; q < 2; q++) {
        int r = r0 + q * 8;
        g_fc2[r * 256 + c] = fmaxf(scl[cl] * sz[r][cl] + shf[cl], 0.f);
    }
}

// block 0: fc3 + log_softmax.  blocks 1..4: zero counters for next run.
__global__ void __launch_bounds__(256) k_mlp3(
    const float* __restrict__ wf3, const float* __restrict__ bf3,
    float* __restrict__ out) {
    int t = threadIdx.x;
    if (blockIdx.x > 0) {
        int g = (blockIdx.x - 1) * 256 + t;        // 1024 threads
        for (int i = g; i < Nn; i += 1024) g_cd[i] = 0ull;
        if (g < 192) { g_sum[g] = 0.f; g_sq[g] = 0.f; }
        g_emb[g] = 0.f;                            // 1024 elements exactly
        return;
    }
    __shared__ float sf[16 * 256];
    __shared__ float sl[16][11];
    for (int i = t; i < 4096; i += 256) sf[i] = g_fc2[i];
    __syncthreads();
    if (t < Bb * NC) {
        int r = t / NC, j = t % NC;
        float a0 = 0.f, a1 = 0.f, a2 = 0.f, a3 = 0.f;
        for (int k = 0; k < 256; k += 4) {
            a0 += sf[r * 256 + k]     * wf3[(k)     * NC + j];
            a1 += sf[r * 256 + k + 1] * wf3[(k + 1) * NC + j];
            a2 += sf[r * 256 + k + 2] * wf3[(k + 2) * NC + j];
            a3 += sf[r * 256 + k + 3] * wf3[(k + 3) * NC + j];
        }
        sl[r][j] = bf3[j] + ((a0 + a1) + (a2 + a3));
    }
    __syncthreads();
    if (t < Bb) {
        float m = -1e30f;
        for (int j = 0; j < NC; j++) m = fmaxf(m, sl[t][j]);
        float s = 0.f;
        for (int j = 0; j < NC; j++) s += expf(sl[t][j] - m);
        float l = m + logf(s);
        for (int j = 0; j < NC; j++) out[t * NC + j] = sl[t][j] - l;
    }
}

// ---------------- launcher ----------------
extern "C" void kernel_launch(void* const* d_in, const int* in_sizes, int n_in,
                              void* d_out, int out_size) {
    const float* x      = (const float*)d_in[0];
    const float* ea     = (const float*)d_in[1];
    const float* w_edge = (const float*)d_in[2];
    const float* b_edge = (const float*)d_in[3];
    const float* w1  = (const float*)d_in[4];  const float* b1  = (const float*)d_in[5];
    const float* g1  = (const float*)d_in[6];  const float* be1 = (const float*)d_in[7];
    const float* w2  = (const float*)d_in[8];  const float* b2  = (const float*)d_in[9];
    const float* g2  = (const float*)d_in[10]; const float* be2 = (const float*)d_in[11];
    const float* g3  = (const float*)d_in[14]; const float* be3 = (const float*)d_in[15];
    const float* w3  = (const float*)d_in[12]; const float* b3  = (const float*)d_in[13];
    const float* wf1 = (const float*)d_in[16]; const float* bf1 = (const float*)d_in[17];
    const float* gf1 = (const float*)d_in[18]; const float* bef1= (const float*)d_in[19];
    const float* wf2 = (const float*)d_in[20]; const float* bf2 = (const float*)d_in[21];
    const float* gf2 = (const float*)d_in[22]; const float* bef2= (const float*)d_in[23];
    const float* wf3 = (const float*)d_in[24]; const float* bf3 = (const float*)d_in[25];
    const int*   ei    = (const int*)d_in[26];
    const int*   batch = (const int*)d_in[27];
    float* out = (float*)d_out;

    float *x16, *z1, *z2, *z3, *sum, *sq;
    cudaGetSymbolAddress((void**)&x16, g_x16);
    cudaGetSymbolAddress((void**)&z1,  g_z1);
    cudaGetSymbolAddress((void**)&z2,  g_z2);
    cudaGetSymbolAddress((void**)&z3,  g_z3);
    cudaGetSymbolAddress((void**)&sum, g_sum);
    cudaGetSymbolAddress((void**)&sq,  g_sq);

    const int T = 256;
    k_edge<<<(Ee + T - 1) / T, T>>>(ea, w_edge, b_edge, ei, x);
    k_scan<<<1, 1024>>>();
    k_scatter<<<(Ee + T - 1) / T, T>>>(ei);

    constexpr int LG = 768;  // 768 blocks * 8 warps; each warp streams 2 rows
    k_layer<16, FIN, Hh, LG><<<LG, T>>>(x16, w1, b1, z1, sum, sq);
    k_norm<Hh><<<Nn * Hh / 4 / T, T>>>(z1, g1, be1, sum, sq);
    k_layer<Hh, Hh, H2, LG><<<LG, T>>>(z1, w2, b2, z2, sum + 64, sq + 64);
    k_norm<H2><<<Nn * H2 / 4 / T, T>>>(z2, g2, be2, sum + 64, sq + 64);
    k_layer<H2, H2, H2, LG><<<LG, T>>>(z2, w3, b3, z3, sum + 128, sq + 128);

    k_pool<<<96, T>>>(z3, batch, g3, be3);

    k_mlp1<<<8, T>>>(wf1, bf1, gf1, bef1, out);
    k_mlp2<<<8, T>>>(wf2, bf2, gf2, bef2);
    k_mlp3<<<5, T>>>(wf3, bf3, out);
}